// round 16
// baseline (speedup 1.0000x reference)
#include <cuda_runtime.h>
#include <cstdint>

#define BATCH 128
#define NPRI  8732
#define NOBJ  16
#define NCLS  21
#define THRESH 0.5f
#define CEB   35        // main blocks per image (256 priors each)

// ---------------- scratch (static device globals; zero-initialized) ----------
__device__ float              g_ce  [BATCH * NPRI];   // full per-prior ce
__device__ uint8_t            g_ct  [BATCH * NPRI];   // conf target (fixup-patched)
__device__ uint8_t            g_of  [BATCH * NPRI];   // matched truth
__device__ unsigned long long g_best[BATCH * NOBJ];   // re-zeroed by k2b each launch
__device__ float              g_pcep[BATCH * CEB];    // per-block posce partials
__device__ float              g_locp[BATCH * CEB];    // per-block loc partials
__device__ float              g_npp [BATCH * CEB];    // per-block npos partials
__device__ float              g_fixp[BATCH];          // fixup deltas
__device__ float              g_fixl[BATCH];
__device__ float              g_fixn[BATCH];
__device__ float              g_nposf[BATCH];
__device__ float              g_locs[BATCH];
__device__ float              g_pces[BATCH];
__device__ float              g_negs[BATCH];
__device__ unsigned int       g_ticket;               // reset by last block each launch

// ---------------- helpers -----------------------------------------------------
__device__ __forceinline__ float sl1(float x) {
    float a = fabsf(x);
    return (a < 1.f) ? 0.5f * a * a : a - 0.5f;
}

// SmoothL1 loc loss of prior pr vs truth tb given prediction lp
__device__ __forceinline__ float locterm(float4 tb, float4 pr, float4 lp) {
    float g0 = ((tb.x + tb.z) * 0.5f - pr.x) / (0.1f * pr.z);
    float g1 = ((tb.y + tb.w) * 0.5f - pr.y) / (0.1f * pr.w);
    float g2 = __logf((tb.z - tb.x) / pr.z) * 5.0f;
    float g3 = __logf((tb.w - tb.y) / pr.w) * 5.0f;
    return sl1(lp.x - g0) + sl1(lp.y - g1) + sl1(lp.z - g2) + sl1(lp.w - g3);
}

// two block-sums for one barrier set; s must hold 64 floats
__device__ __forceinline__ float2 brSum2F(float a, float b, float* s) {
    int lane = threadIdx.x & 31, wid = threadIdx.x >> 5;
    int nw = (blockDim.x + 31) >> 5;
    #pragma unroll
    for (int o = 16; o; o >>= 1) {
        a += __shfl_xor_sync(0xFFFFFFFFu, a, o);
        b += __shfl_xor_sync(0xFFFFFFFFu, b, o);
    }
    if (lane == 0) { s[wid] = a; s[32 + wid] = b; }
    __syncthreads();
    if (wid == 0) {
        float ra = (lane < nw) ? s[lane] : 0.f;
        float rb = (lane < nw) ? s[32 + lane] : 0.f;
        #pragma unroll
        for (int o = 16; o; o >>= 1) {
            ra += __shfl_xor_sync(0xFFFFFFFFu, ra, o);
            rb += __shfl_xor_sync(0xFFFFFFFFu, rb, o);
        }
        if (lane == 0) { s[0] = ra; s[32] = rb; }
    }
    __syncthreads();
    float2 r = make_float2(s[0], s[32]);
    __syncthreads();
    return r;
}

// ---------------- K2: conf stream + inline matching + ce + loc -----------------
// grid BATCH*CEB x 256. IoU compute hides under the conf DRAM stream.
__global__ __launch_bounds__(256)
void k2_main(const float* __restrict__ conf, const int* __restrict__ labels,
             const float* __restrict__ loc_preds, const float* __restrict__ boxes,
             const float* __restrict__ priors) {
    const int blk = blockIdx.x;
    const int b   = blk / CEB;
    const int t   = blk % CEB;
    const int tid = threadIdx.x;
    const int lane = tid & 31, wid = tid >> 5;
    const int r0  = t * 256;
    const int nr  = min(256, NPRI - r0);
    const bool valid = (tid < nr);

    __shared__ float  s_rows[256 * NCLS];
    __shared__ float  s_v[256][NOBJ + 1];   // transpose for per-truth reduce
    __shared__ float4 s_t[NOBJ];
    __shared__ float  s_ta[NOBJ];
    __shared__ int    s_lab[NOBJ];
    __shared__ float  s_redf[64];

    if (tid < NOBJ) {
        float4 tb = ((const float4*)boxes)[b * NOBJ + tid];
        s_t[tid]  = tb;
        s_ta[tid] = (tb.z - tb.x) * (tb.w - tb.y);
        s_lab[tid] = labels[b * NOBJ + tid];
    }
    const int nf4 = nr * NCLS / 4;
    const float4* src = (const float4*)(conf + ((size_t)b * NPRI + r0) * NCLS);
    #pragma unroll
    for (int i = 0; i < 6; i++) {
        int j = tid + i * 256;
        if (j < nf4) ((float4*)s_rows)[j] = src[j];
    }
    __syncthreads();

    // ---- per-prior argmax over truths + transpose store ----
    float px1 = 2.f, py1 = 2.f, px2 = 2.f, py2 = 2.f, ap = 0.f;
    if (valid) {
        float4 pr = ((const float4*)priors)[r0 + tid];
        float hw = 0.5f * pr.z, hh = 0.5f * pr.w;
        px1 = pr.x - hw; py1 = pr.y - hh; px2 = pr.x + hw; py2 = pr.y + hh;
        ap = pr.z * pr.w;
    }
    float pv = -1.f; int po = 0;
    #pragma unroll
    for (int o = 0; o < NOBJ; o++) {
        float4 tb = s_t[o];
        float ix = fmaxf(fminf(tb.z, px2) - fmaxf(tb.x, px1), 0.f);
        float iy = fmaxf(fminf(tb.w, py2) - fmaxf(tb.y, py1), 0.f);
        float in = ix * iy;
        float v  = valid ? __fdividef(in, (s_ta[o] + ap) - in) : -1.f;
        s_v[tid][o] = v;                       // pad 17: conflict-free
        bool g = v > pv;                       // first truth on tie
        pv = g ? v : pv;  po = g ? o : po;
    }
    __syncthreads();                           // s_v complete

    // ---- per-prior ce / targets / loc (unforced) ----
    float posce = 0.f, locsum = 0.f; int isp = 0;
    if (valid) {
        float ov = pv;
        if (fabsf(ov - 0.5f) < 1e-3f) {        // exact near threshold
            float4 tb = s_t[po];
            float ix = fmaxf(fminf(tb.z, px2) - fmaxf(tb.x, px1), 0.f);
            float iy = fmaxf(fminf(tb.w, py2) - fmaxf(tb.y, py1), 0.f);
            float in = ix * iy;
            ov = in / ((s_ta[po] + ap) - in);
        }
        int ct = (ov < THRESH) ? 0 : (s_lab[po] + 1);
        size_t idx = (size_t)b * NPRI + (r0 + tid);
        const float* v = s_rows + tid * NCLS;  // stride 21: conflict-free
        float m = v[0];
        #pragma unroll
        for (int c = 1; c < NCLS; c++) m = fmaxf(m, v[c]);
        float ssum = 0.f;
        #pragma unroll
        for (int c = 0; c < NCLS; c++) ssum += __expf(v[c] - m);
        float ce = m + __logf(ssum) - v[ct];
        g_ce[idx] = ce;                        // full ce (k3 masks via g_ct)
        g_ct[idx] = (uint8_t)ct;
        g_of[idx] = (uint8_t)po;
        if (ct > 0) {
            posce = ce; isp = 1;
            float4 pr4 = ((const float4*)priors)[r0 + tid];
            locsum = locterm(s_t[po], pr4, ((const float4*)loc_preds)[idx]);
        }
    }

    // ---- per-truth block best: 8 warps x 2 columns ----
    #pragma unroll
    for (int rep = 0; rep < 2; rep++) {
        const int o = wid * 2 + rep;
        float bv = -1.f; int bi = 0;
        #pragma unroll
        for (int k = 0; k < 8; k++) {
            int i = lane + k * 32;
            float v = s_v[i][o];
            bool g = v > bv;                   // ascending i: smallest i on tie
            bv = g ? v : bv;  bi = g ? i : bi;
        }
        #pragma unroll
        for (int off = 16; off; off >>= 1) {
            float ovv = __shfl_xor_sync(0xFFFFFFFFu, bv, off);
            int   oii = __shfl_xor_sync(0xFFFFFFFFu, bi, off);
            bool take = (ovv > bv) || (ovv == bv && oii < bi);
            bv = take ? ovv : bv;  bi = take ? oii : bi;
        }
        if (lane == 0 && bv >= 0.f) {
            unsigned long long key =
                ((unsigned long long)__float_as_uint(bv) << 32) |
                (unsigned)(0xFFFFFFFFu - (unsigned)(r0 + bi));
            atomicMax(&g_best[b * NOBJ + o], key);
        }
    }

    float2 pl = brSum2F(posce, locsum, s_redf);
    float2 nn = brSum2F((float)isp, 0.f, s_redf);
    if (tid == 0) {
        g_pcep[blk] = pl.x;
        g_locp[blk] = pl.y;
        g_npp [blk] = nn.x;
    }
}

// ---------------- K2b: force-assign fixup (1 warp per image) ------------------
__global__ __launch_bounds__(256)
void k2b_fix(const float* __restrict__ conf, const int* __restrict__ labels,
             const float* __restrict__ loc_preds, const float* __restrict__ boxes,
             const float* __restrict__ priors) {
    const int tid  = threadIdx.x;
    const int lane = tid & 31;
    const int b    = blockIdx.x * 8 + (tid >> 5);
    if (b >= BATCH) return;

    unsigned fp = 0xFFFFFFFFu;
    int lab = 0;
    if (lane < NOBJ) {
        unsigned long long key = g_best[b * NOBJ + lane];
        fp  = 0xFFFFFFFFu - (unsigned)(key & 0xFFFFFFFFULL);
        lab = labels[b * NOBJ + lane];
        g_best[b * NOBJ + lane] = 0ULL;        // re-zero for next graph replay
    }
    // dedupe: later truth (larger lane) wins on shared prior
    bool fin = (lane < NOBJ);
    #pragma unroll
    for (int j = 0; j < NOBJ; j++) {
        unsigned fpj = __shfl_sync(0xFFFFFFFFu, fp, j);
        if (lane < NOBJ && j > lane && fpj == fp) fin = false;
    }

    float dpos = 0.f, dloc = 0.f, dnp = 0.f;
    if (fin) {
        int p = (int)fp;
        size_t idx = (size_t)b * NPRI + p;
        int   ct_u = g_ct[idx];
        int   o_u  = g_of[idx];
        float ce_u = g_ce[idx];
        int   ctf  = lab + 1;
        float vc = conf[idx * NCLS + ct_u];
        float vf = conf[idx * NCLS + ctf];
        float ce_f = ce_u + vc - vf;           // = logsum - v[ctf] (±1 ulp)
        float4 pr = ((const float4*)priors)[p];
        float4 lp = ((const float4*)loc_preds)[idx];
        float4 tb = ((const float4*)boxes)[b * NOBJ + lane];
        dpos = ce_f; dnp = 1.f;
        dloc = locterm(tb, pr, lp);
        if (ct_u > 0) {                        // remove unforced positive contrib
            dpos -= ce_u; dnp -= 1.f;
            float4 tbo = ((const float4*)boxes)[b * NOBJ + o_u];
            dloc -= locterm(tbo, pr, lp);
        }
        g_ct[idx] = (uint8_t)ctf;              // forced: positive for k3
    }
    #pragma unroll
    for (int off = 16; off; off >>= 1) {
        dpos += __shfl_xor_sync(0xFFFFFFFFu, dpos, off);
        dloc += __shfl_xor_sync(0xFFFFFFFFu, dloc, off);
        dnp  += __shfl_xor_sync(0xFFFFFFFFu, dnp,  off);
    }
    if (lane == 0) {
        g_fixp[b] = dpos;
        g_fixl[b] = dloc;
        g_fixn[b] = dnp;
    }
}

// ---------------- K3: partial merge + top-K select + fused final ---------------
__global__ __launch_bounds__(1024)
void k3_select(float* __restrict__ out) {
    const int b    = blockIdx.x;
    const int tid  = threadIdx.x;
    const int lane = tid & 31, wid = tid >> 5;

    __shared__ float s_redf[64];
    __shared__ int   s_cnt[2][3][32];
    __shared__ int   s_bc[4];

    // merge per-block partials + fix deltas
    float pp = 0.f, lp = 0.f, np = 0.f;
    if (tid < CEB) {
        pp = g_pcep[b * CEB + tid];
        lp = g_locp[b * CEB + tid];
        np = g_npp [b * CEB + tid];
    } else if (tid == CEB) {
        pp = g_fixp[b];
        lp = g_fixl[b];
        np = g_fixn[b];
    }
    float2 m1 = brSum2F(np, pp, s_redf);
    float2 m2 = brSum2F(lp, 0.f, s_redf);
    const int   npos = (int)m1.x;
    const float pcT  = m1.y, lcT = m2.x;

    unsigned u[9];
    #pragma unroll
    for (int i = 0; i < 9; i++) {
        int p = tid + i * 1024;
        u[i] = 0u;
        if (p < NPRI) {
            size_t idx = (size_t)b * NPRI + p;
            if (g_ct[idx] == 0)                // negatives only
                u[i] = __float_as_uint(g_ce[idx]);
        }
    }

    int K = 3 * npos; if (K > NPRI) K = NPRI;
    float negsum = 0.f;
    if (K > 0) {
        unsigned prefix = 0u;
        int par = 0;
        for (int sh = 29; sh >= 1; sh -= 2) {     // 2 bits/round, 1 barrier
            unsigned cA = prefix | (1u << sh);
            unsigned cB = prefix | (2u << sh);
            unsigned cC = prefix | (3u << sh);
            int n1 = 0, n2 = 0, n3 = 0;
            #pragma unroll
            for (int i = 0; i < 9; i++) {
                n1 += (u[i] >= cA);
                n2 += (u[i] >= cB);
                n3 += (u[i] >= cC);
            }
            n1 = __reduce_add_sync(0xFFFFFFFFu, n1);
            n2 = __reduce_add_sync(0xFFFFFFFFu, n2);
            n3 = __reduce_add_sync(0xFFFFFFFFu, n3);
            if (lane == 0) {
                s_cnt[par][0][wid] = n1;
                s_cnt[par][1][wid] = n2;
                s_cnt[par][2][wid] = n3;
            }
            __syncthreads();
            int t1 = __reduce_add_sync(0xFFFFFFFFu, s_cnt[par][0][lane]);
            int t2 = __reduce_add_sync(0xFFFFFFFFu, s_cnt[par][1][lane]);
            int t3 = __reduce_add_sync(0xFFFFFFFFu, s_cnt[par][2][lane]);
            prefix |= (t3 >= K) ? (3u << sh)
                    : (t2 >= K) ? (2u << sh)
                    : (t1 >= K) ? (1u << sh) : 0u;
            par ^= 1;
        }
        {   // final bit 0
            unsigned cand = prefix | 1u;
            int n = 0;
            #pragma unroll
            for (int i = 0; i < 9; i++) n += (u[i] >= cand);
            n = __reduce_add_sync(0xFFFFFFFFu, n);
            if (lane == 0) s_cnt[par][0][wid] = n;
            __syncthreads();
            int tot = __reduce_add_sync(0xFFFFFFFFu, s_cnt[par][0][lane]);
            if (tot >= K) prefix |= 1u;
        }
        float vK = __uint_as_float(prefix);       // exact K-th largest
        float sgt = 0.f; int cgt = 0;
        #pragma unroll
        for (int i = 0; i < 9; i++) {
            float v = __uint_as_float(u[i]);
            if (v > vK) { sgt += v; cgt++; }
        }
        float2 sc = brSum2F(sgt, (float)cgt, s_redf);   // cgt < 2^24: exact
        negsum = sc.x + ((float)K - sc.y) * vK;         // ties handled exactly
    }

    if (tid == 0) {
        g_locs[b]  = lcT;
        g_pces[b]  = pcT;
        g_negs[b]  = negsum;
        g_nposf[b] = (float)npos;
    }
    __threadfence();
    __syncthreads();
    if (tid == 0) {
        unsigned old = atomicAdd(&g_ticket, 1u);
        s_bc[2] = (old == BATCH - 1) ? 1 : 0;
    }
    __syncthreads();

    if (s_bc[2]) {   // last block: final reduction over images
        float np2 = 0.f, lc = 0.f, pc = 0.f, ns = 0.f;
        if (tid < BATCH) {
            np2 = __ldcg(&g_nposf[tid]);
            lc  = __ldcg(&g_locs[tid]);
            pc  = __ldcg(&g_pces[tid]);
            ns  = __ldcg(&g_negs[tid]);
        }
        float2 r1 = brSum2F(np2, lc, s_redf);
        float2 r2 = brSum2F(pc, ns, s_redf);
        if (tid == 0) {
            out[0] = (r2.x + r2.y) / (r1.x + 1e-7f) + r1.y / (4.0f * r1.x);
            g_ticket = 0u;
        }
    }
}

// ---------------- launch ------------------------------------------------------
extern "C" void kernel_launch(void* const* d_in, const int* in_sizes, int n_in,
                              void* d_out, int out_size) {
    const float* loc_preds  = (const float*)d_in[0];
    const float* conf_preds = (const float*)d_in[1];
    const float* boxes      = (const float*)d_in[2];
    const int*   labels     = (const int*)d_in[3];
    const float* priors     = (const float*)d_in[4];
    float* out = (float*)d_out;

    k2_main<<<BATCH * CEB, 256>>>(conf_preds, labels, loc_preds, boxes, priors);
    k2b_fix<<<16, 256>>>(conf_preds, labels, loc_preds, boxes, priors);
    k3_select<<<BATCH, 1024>>>(out);
    (void)in_sizes; (void)n_in; (void)out_size;
}

// round 17
// speedup vs baseline: 1.0781x; 1.0781x over previous
#include <cuda_runtime.h>
#include <cstdint>

#define BATCH 128
#define NPRI  8732
#define NOBJ  16
#define NCLS  21
#define THRESH 0.5f
#define K1B   9         // k1 blocks per image (1024 priors each; 9*1024 >= 8732)
#define CEB   35        // k2 blocks per image (256 priors each)

// ---------------- scratch (static device globals; zero-initialized) ----------
__device__ float              g_btov[BATCH * NPRI];
__device__ uint8_t            g_bti [BATCH * NPRI];
__device__ float              g_ce  [BATCH * NPRI];   // neg_loss (0 for positives)
__device__ unsigned long long g_best[BATCH * NOBJ];   // re-zeroed by k3 each launch
__device__ float              g_pcep[BATCH * CEB];    // per-block posce partials
__device__ float              g_locp[BATCH * CEB];    // per-block loc partials
__device__ float              g_npp [BATCH * CEB];    // per-block npos partials
__device__ float              g_nposf[BATCH];
__device__ float              g_locs[BATCH];
__device__ float              g_pces[BATCH];
__device__ float              g_negs[BATCH];
__device__ unsigned int       g_ticket;               // reset by last block each launch

// ---------------- helpers -----------------------------------------------------
__device__ __forceinline__ float sl1(float x) {
    float a = fabsf(x);
    return (a < 1.f) ? 0.5f * a * a : a - 0.5f;
}

// two block-sums for one barrier set; s must hold 64 floats
__device__ __forceinline__ float2 brSum2F(float a, float b, float* s) {
    int lane = threadIdx.x & 31, wid = threadIdx.x >> 5;
    int nw = (blockDim.x + 31) >> 5;
    #pragma unroll
    for (int o = 16; o; o >>= 1) {
        a += __shfl_xor_sync(0xFFFFFFFFu, a, o);
        b += __shfl_xor_sync(0xFFFFFFFFu, b, o);
    }
    if (lane == 0) { s[wid] = a; s[32 + wid] = b; }
    __syncthreads();
    if (wid == 0) {
        float ra = (lane < nw) ? s[lane] : 0.f;
        float rb = (lane < nw) ? s[32 + lane] : 0.f;
        #pragma unroll
        for (int o = 16; o; o >>= 1) {
            ra += __shfl_xor_sync(0xFFFFFFFFu, ra, o);
            rb += __shfl_xor_sync(0xFFFFFFFFu, rb, o);
        }
        if (lane == 0) { s[0] = ra; s[32] = rb; }
    }
    __syncthreads();
    float2 r = make_float2(s[0], s[32]);
    __syncthreads();
    return r;
}

// ---------------- K1: matching, 4 priors/thread, collective-free mainloop -----
__global__ __launch_bounds__(256)
void k1_match(const float* __restrict__ boxes, const float* __restrict__ priors) {
    const int b    = blockIdx.x / K1B;
    const int t    = blockIdx.x % K1B;
    const int tid  = threadIdx.x;
    const int lane = tid & 31, wid = tid >> 5;
    const int base = t * 1024;

    __shared__ float4 s_t[NOBJ];
    __shared__ float  s_ta[NOBJ];
    __shared__ unsigned long long s_red[NOBJ][8];

    if (tid < NOBJ) {
        float4 tb = ((const float4*)boxes)[b * NOBJ + tid];
        s_t[tid]  = tb;
        s_ta[tid] = (tb.z - tb.x) * (tb.w - tb.y);
    }
    __syncthreads();

    int   P[4];  bool ok[4];
    float x1[4], y1[4], x2[4], y2[4], ar[4];
    #pragma unroll
    for (int q = 0; q < 4; q++) {
        P[q]  = base + q * 256 + tid;
        ok[q] = (P[q] < NPRI);
        // invalid -> far degenerate box: inter = 0 -> v = 0 (uint 0, loses max)
        x1[q] = 2.f; y1[q] = 2.f; x2[q] = 2.f; y2[q] = 2.f; ar[q] = 0.f;
        if (ok[q]) {
            float4 pr = ((const float4*)priors)[P[q]];
            float hw = 0.5f * pr.z, hh = 0.5f * pr.w;
            x1[q] = pr.x - hw; y1[q] = pr.y - hh;
            x2[q] = pr.x + hw; y2[q] = pr.y + hh;
            ar[q] = pr.z * pr.w;
        }
    }

    unsigned bv[NOBJ];
    #pragma unroll
    for (int o = 0; o < NOBJ; o++) bv[o] = 0u;
    float pv[4] = {-1.f, -1.f, -1.f, -1.f};
    int   po[4] = {0, 0, 0, 0};

    #pragma unroll
    for (int o = 0; o < NOBJ; o++) {
        float4 tb = s_t[o]; float ta = s_ta[o];
        #pragma unroll
        for (int q = 0; q < 4; q++) {
            float ix = fmaxf(fminf(tb.z, x2[q]) - fmaxf(tb.x, x1[q]), 0.f);
            float iy = fmaxf(fminf(tb.w, y2[q]) - fmaxf(tb.y, y1[q]), 0.f);
            float in = ix * iy;
            float v  = __fdividef(in, (ta + ar[q]) - in);   // ordering only; >= 0
            bool g = v > pv[q];                             // first truth on tie
            pv[q] = g ? v : pv[q];  po[q] = g ? o : po[q];
            bv[o] = max(bv[o], __float_as_uint(v));         // 1 IMNMX per pair
        }
    }

    // finalize per truth: one REDUX + one ballot each, winner recovers index
    #pragma unroll
    for (int o = 0; o < NOBJ; o++) {
        unsigned vm  = __reduce_max_sync(0xFFFFFFFFu, bv[o]);
        unsigned msk = __ballot_sync(0xFFFFFFFFu, bv[o] == vm);
        if (lane == __ffs(msk) - 1) {
            float4 tb = s_t[o]; float ta = s_ta[o];
            int wq = 0;
            #pragma unroll
            for (int q = 3; q >= 0; q--) {      // descending: keep smallest q
                float ix = fmaxf(fminf(tb.z, x2[q]) - fmaxf(tb.x, x1[q]), 0.f);
                float iy = fmaxf(fminf(tb.w, y2[q]) - fmaxf(tb.y, y1[q]), 0.f);
                float in = ix * iy;
                float v  = __fdividef(in, (ta + ar[q]) - in);  // bit-identical
                if (__float_as_uint(v) == vm) wq = q;
            }
            s_red[o][wid] = ((unsigned long long)vm << 32)
                          | (unsigned)(0xFFFFFFFFu - (unsigned)P[wq]);
        }
    }

    // per-prior store; exact div.rn only near the 0.5 threshold
    #pragma unroll
    for (int q = 0; q < 4; q++) {
        if (!ok[q]) continue;
        float ov = pv[q];
        if (fabsf(ov - 0.5f) < 1e-3f) {
            float4 tb = s_t[po[q]];
            float ix = fmaxf(fminf(tb.z, x2[q]) - fmaxf(tb.x, x1[q]), 0.f);
            float iy = fmaxf(fminf(tb.w, y2[q]) - fmaxf(tb.y, y1[q]), 0.f);
            float in = ix * iy;
            ov = in / ((s_ta[po[q]] + ar[q]) - in);
        }
        g_btov[b * NPRI + P[q]] = ov;
        g_bti [b * NPRI + P[q]] = (uint8_t)po[q];
    }

    __syncthreads();
    if (tid < NOBJ) {
        unsigned long long m = 0ULL;
        #pragma unroll
        for (int w = 0; w < 8; w++) {
            unsigned long long u = s_red[tid][w];
            m = (u > m) ? u : m;
        }
        atomicMax(&g_best[b * NOBJ + tid], m);
    }
}

// ---------------- K2: ce + targets + loc loss, per-block partials (R15) -------
__global__ __launch_bounds__(256)
void k2_ce(const float* __restrict__ conf, const int* __restrict__ labels,
           const float* __restrict__ loc_preds, const float* __restrict__ boxes,
           const float* __restrict__ priors) {
    const int blk = blockIdx.x;
    const int b   = blk / CEB;
    const int t   = blk % CEB;
    const int tid = threadIdx.x;
    const int r0  = t * 256;
    const int nr  = min(256, NPRI - r0);

    __shared__ float    s_rows[256 * NCLS];
    __shared__ float4   s_t[NOBJ];
    __shared__ int      s_lab[NOBJ];
    __shared__ unsigned s_fp[NOBJ];
    __shared__ float    s_redf[64];

    if (tid < NOBJ) {
        s_t[tid]   = ((const float4*)boxes)[b * NOBJ + tid];
        s_lab[tid] = labels[b * NOBJ + tid];
        s_fp[tid]  = 0xFFFFFFFFu - (unsigned)(g_best[b * NOBJ + tid] & 0xFFFFFFFFULL);
    }
    const int nf4 = nr * NCLS / 4;
    const float4* src = (const float4*)(conf + ((size_t)b * NPRI + r0) * NCLS);
    #pragma unroll
    for (int i = 0; i < 6; i++) {
        int j = tid + i * 256;
        if (j < nf4) ((float4*)s_rows)[j] = src[j];
    }
    __syncthreads();

    float posce = 0.f, locsum = 0.f;
    int isp = 0;
    if (tid < nr) {
        int p = r0 + tid;
        size_t idx = (size_t)b * NPRI + p;
        float ov = g_btov[idx];
        int   o  = g_bti[idx];
        #pragma unroll
        for (int oo = 0; oo < NOBJ; oo++) {          // ascending: last truth wins
            bool f = (s_fp[oo] == (unsigned)p);
            ov = f ? 2.0f : ov;
            o  = f ? oo : o;
        }
        int ct = (ov < THRESH) ? 0 : (s_lab[o] + 1);
        const float* v = s_rows + tid * NCLS;        // stride 21: conflict-free
        float m = v[0];
        #pragma unroll
        for (int c = 1; c < NCLS; c++) m = fmaxf(m, v[c]);
        float ssum = 0.f;
        #pragma unroll
        for (int c = 0; c < NCLS; c++) ssum += __expf(v[c] - m);
        float ce = m + __logf(ssum) - v[ct];
        if (ct > 0) {
            posce = ce; isp = 1;
            float4 tb = s_t[o];
            float4 pr = ((const float4*)priors)[p];
            float g0 = ((tb.x + tb.z) * 0.5f - pr.x) / (0.1f * pr.z);
            float g1 = ((tb.y + tb.w) * 0.5f - pr.y) / (0.1f * pr.w);
            float g2 = __logf((tb.z - tb.x) / pr.z) * 5.0f;
            float g3 = __logf((tb.w - tb.y) / pr.w) * 5.0f;
            float4 lp = ((const float4*)loc_preds)[idx];
            locsum = sl1(lp.x - g0) + sl1(lp.y - g1)
                   + sl1(lp.z - g2) + sl1(lp.w - g3);
            ce = 0.f;                                 // neg_loss = 0 for positives
        }
        g_ce[idx] = ce;
    }
    float2 pl = brSum2F(posce, locsum, s_redf);
    float2 nn = brSum2F((float)isp, 0.f, s_redf);
    if (tid == 0) {
        g_pcep[blk] = pl.x;
        g_locp[blk] = pl.y;
        g_npp [blk] = nn.x;
    }
}

// ---------------- K3: lean top-K select + partial merge + fused final (R15) ---
__global__ __launch_bounds__(1024)
void k3_select(float* __restrict__ out) {
    const int b    = blockIdx.x;
    const int tid  = threadIdx.x;
    const int lane = tid & 31, wid = tid >> 5;

    __shared__ float s_redf[64];
    __shared__ int   s_cnt[2][3][32];
    __shared__ int   s_bc[4];

    // merge per-block partials (35 per image)
    float pp = 0.f, lp = 0.f, np = 0.f;
    if (tid < CEB) {
        pp = g_pcep[b * CEB + tid];
        lp = g_locp[b * CEB + tid];
        np = g_npp [b * CEB + tid];
    }
    float2 m1 = brSum2F(np, pp, s_redf);
    float2 m2 = brSum2F(lp, 0.f, s_redf);
    const int   npos = (int)m1.x;
    const float pcT  = m1.y, lcT = m2.x;

    unsigned u[9];
    #pragma unroll
    for (int i = 0; i < 9; i++) {
        int p = tid + i * 1024;
        u[i] = (p < NPRI) ? __float_as_uint(g_ce[(size_t)b * NPRI + p]) : 0u;
    }

    int K = 3 * npos; if (K > NPRI) K = NPRI;
    float negsum = 0.f;
    if (K > 0) {
        unsigned prefix = 0u;
        int par = 0;
        for (int sh = 29; sh >= 1; sh -= 2) {     // 2 bits/round, 1 barrier
            unsigned cA = prefix | (1u << sh);
            unsigned cB = prefix | (2u << sh);
            unsigned cC = prefix | (3u << sh);
            int n1 = 0, n2 = 0, n3 = 0;
            #pragma unroll
            for (int i = 0; i < 9; i++) {
                n1 += (u[i] >= cA);
                n2 += (u[i] >= cB);
                n3 += (u[i] >= cC);
            }
            n1 = __reduce_add_sync(0xFFFFFFFFu, n1);
            n2 = __reduce_add_sync(0xFFFFFFFFu, n2);
            n3 = __reduce_add_sync(0xFFFFFFFFu, n3);
            if (lane == 0) {
                s_cnt[par][0][wid] = n1;
                s_cnt[par][1][wid] = n2;
                s_cnt[par][2][wid] = n3;
            }
            __syncthreads();
            int t1 = __reduce_add_sync(0xFFFFFFFFu, s_cnt[par][0][lane]);
            int t2 = __reduce_add_sync(0xFFFFFFFFu, s_cnt[par][1][lane]);
            int t3 = __reduce_add_sync(0xFFFFFFFFu, s_cnt[par][2][lane]);
            prefix |= (t3 >= K) ? (3u << sh)
                    : (t2 >= K) ? (2u << sh)
                    : (t1 >= K) ? (1u << sh) : 0u;
            par ^= 1;
        }
        {   // final bit 0
            unsigned cand = prefix | 1u;
            int n = 0;
            #pragma unroll
            for (int i = 0; i < 9; i++) n += (u[i] >= cand);
            n = __reduce_add_sync(0xFFFFFFFFu, n);
            if (lane == 0) s_cnt[par][0][wid] = n;
            __syncthreads();
            int tot = __reduce_add_sync(0xFFFFFFFFu, s_cnt[par][0][lane]);
            if (tot >= K) prefix |= 1u;
        }
        float vK = __uint_as_float(prefix);       // exact K-th largest
        float sgt = 0.f; int cgt = 0;
        #pragma unroll
        for (int i = 0; i < 9; i++) {
            float v = __uint_as_float(u[i]);
            if (v > vK) { sgt += v; cgt++; }
        }
        float2 sc = brSum2F(sgt, (float)cgt, s_redf);   // cgt < 2^24: exact
        negsum = sc.x + ((float)K - sc.y) * vK;         // ties handled exactly
    }

    if (tid == 0) {
        g_locs[b]  = lcT;
        g_pces[b]  = pcT;
        g_negs[b]  = negsum;
        g_nposf[b] = (float)npos;
    }
    if (tid < NOBJ) g_best[b * NOBJ + tid] = 0ULL;   // re-zero for graph replay

    __threadfence();
    __syncthreads();
    if (tid == 0) {
        unsigned old = atomicAdd(&g_ticket, 1u);
        s_bc[2] = (old == BATCH - 1) ? 1 : 0;
    }
    __syncthreads();

    if (s_bc[2]) {   // last block: final reduction over images
        float np2 = 0.f, lc = 0.f, pc = 0.f, ns = 0.f;
        if (tid < BATCH) {
            np2 = __ldcg(&g_nposf[tid]);
            lc  = __ldcg(&g_locs[tid]);
            pc  = __ldcg(&g_pces[tid]);
            ns  = __ldcg(&g_negs[tid]);
        }
        float2 r1 = brSum2F(np2, lc, s_redf);
        float2 r2 = brSum2F(pc, ns, s_redf);
        if (tid == 0) {
            out[0] = (r2.x + r2.y) / (r1.x + 1e-7f) + r1.y / (4.0f * r1.x);
            g_ticket = 0u;
        }
    }
}

// ---------------- launch ------------------------------------------------------
extern "C" void kernel_launch(void* const* d_in, const int* in_sizes, int n_in,
                              void* d_out, int out_size) {
    const float* loc_preds  = (const float*)d_in[0];
    const float* conf_preds = (const float*)d_in[1];
    const float* boxes      = (const float*)d_in[2];
    const int*   labels     = (const int*)d_in[3];
    const float* priors     = (const float*)d_in[4];
    float* out = (float*)d_out;

    k1_match<<<BATCH * K1B, 256>>>(boxes, priors);
    k2_ce<<<BATCH * CEB, 256>>>(conf_preds, labels, loc_preds, boxes, priors);
    k3_select<<<BATCH, 1024>>>(out);
    (void)in_sizes; (void)n_in; (void)out_size;
}